// round 13
// baseline (speedup 1.0000x reference)
#include <cuda_runtime.h>

#define B_N   1024
#define C_N   128
#define I_N   16
#define E_N   10
#define NT3   816           // cubic monomials i0<=i1<=i2
#define NT2   136           // quadratic monomials
#define NT    968           // 816 + 136 + 16
#define NCOMP 4             // L=0 scalar + 3 components of L=1
#define NPMAX 640           // >= max possible pairs (517)

// ---------------- device scratch (static globals; no allocation) ----------------
__device__ int   g_pA[NPMAX];
__device__ int   g_pB[NPMAX];
__device__ int   g_pE[NPMAX];
__device__ int   g_npairs;
__device__ __align__(32) float g_U3S[NCOMP][NT3][8];
__device__ __align__(16) float g_U2S[NCOMP][NT2][4];
__device__ float g_U1S[NCOMP][I_N];

// ---------------- kernel A: sort+pair (block 0) + U sym (blocks 1..32) ----------
__global__ void prep_kernel(const float* __restrict__ node_attrs,
                            const float* __restrict__ U3_l0,
                            const float* __restrict__ U3_l1,
                            const float* __restrict__ U2_l0,
                            const float* __restrict__ U2_l1,
                            const float* __restrict__ U1_l0,
                            const float* __restrict__ U1_l1) {
    int tid = threadIdx.x;   // 1024
    if (blockIdx.x == 0) {
        __shared__ int s_hist[E_N], s_off[E_N], s_start[E_N], s_end[E_N], s_pbase[E_N];
        __shared__ int s_perm[B_N];
        if (tid < E_N) s_hist[tid] = 0;
        __syncthreads();
        const float* na = node_attrs + tid * E_N;
        int e = 0;
#pragma unroll
        for (int j = 0; j < E_N; j++) if (na[j] > 0.5f) e = j;
        atomicAdd(&s_hist[e], 1);
        __syncthreads();
        if (tid == 0) {
            int acc = 0, pacc = 0;
            for (int j = 0; j < E_N; j++) {
                s_start[j] = acc; s_off[j] = acc; s_pbase[j] = pacc;
                pacc += (s_hist[j] + 1) >> 1;
                acc  += s_hist[j];
                s_end[j] = acc;
            }
            g_npairs = pacc;
        }
        __syncthreads();
        int pos = atomicAdd(&s_off[e], 1);
        s_perm[pos] = tid;
        __syncthreads();
        int off = pos - s_start[e];
        if ((off & 1) == 0) {
            int p    = s_pbase[e] + (off >> 1);
            int posB = (pos + 1 < s_end[e]) ? pos + 1 : pos;  // odd tail: self-pair
            g_pA[p] = tid;
            g_pB[p] = s_perm[posB];
            g_pE[p] = e;
        }
        return;
    }

    int gtid = (blockIdx.x - 1) * blockDim.x + tid;   // 0..32767

    if (gtid < NCOMP * NT3 * 8) {
        int k    = gtid & 7;
        int t    = (gtid >> 3) % NT3;
        int comp = gtid / (NT3 * 8);
        int rem = t, a = 0;
        for (int ap = 0; ap < I_N; ap++) {
            int sz = (I_N - ap) * (I_N - ap + 1) / 2;
            if (rem < sz) { a = ap; break; }
            rem -= sz;
        }
        int b = a;
        for (int bp = a; bp < I_N; bp++) {
            int sz = I_N - bp;
            if (rem < sz) { b = bp; break; }
            rem -= sz;
        }
        int c = b + rem;
        float inv = (a == c) ? (1.f / 6.f) : ((a == b || b == c) ? 0.5f : 1.f);
        int kN; const float* U;
        if (comp == 0) { kN = 5; U = U3_l0; }
        else           { kN = 7; U = U3_l1 + (comp - 1) * (I_N * I_N * I_N * 7); }
        float s = 0.f;
        if (k < kN) {
            auto at = [&](int i0, int i1, int i2) {
                return U[((i0 * I_N + i1) * I_N + i2) * kN + k];
            };
            s = at(a,b,c) + at(a,c,b) + at(b,a,c) + at(b,c,a) + at(c,a,b) + at(c,b,a);
            s *= inv;
        }
        g_U3S[comp][t][k] = s;
    }
    if (gtid < NCOMP * NT2 * 4) {
        int k    = gtid & 3;
        int t    = (gtid >> 2) % NT2;
        int comp = gtid / (NT2 * 4);
        int rem = t, a = 0;
        for (int ap = 0; ap < I_N; ap++) {
            int sz = I_N - ap;
            if (rem < sz) { a = ap; break; }
            rem -= sz;
        }
        int b = a + rem;
        int kN; const float* U;
        if (comp == 0) { kN = 2; U = U2_l0; }
        else           { kN = 3; U = U2_l1 + (comp - 1) * (I_N * I_N * 3); }
        float s = 0.f;
        if (k < kN) {
            s = U[(a * I_N + b) * kN + k];
            if (a != b) s += U[(b * I_N + a) * kN + k];
        }
        g_U2S[comp][t][k] = s;
    }
    if (gtid < NCOMP * I_N) {
        int comp = gtid / I_N, i = gtid % I_N;
        g_U1S[comp][i] = (comp == 0) ? U1_l0[i] : U1_l1[(comp - 1) * I_N + i];
    }
}

// ---------------- kernel B: fused fold + evaluation, block = channel ------------
// 640 threads. Prologue folds W into all 10 species' slabs in SMEM (reads
// L2-resident g_U3S once per block). Eval: thread p handles same-species item
// pair (g_pA[p], g_pB[p]) -> each coefficient LDS.128 feeds 8 FFMA, halving
// L1 wavefront pressure (R12: L1=71.6% binding at 1 item/thread).
__global__ void __launch_bounds__(NPMAX, 1) main_kernel(const float* __restrict__ a_i,
                                                        const float* __restrict__ W3_l0,
                                                        const float* __restrict__ W2_l0,
                                                        const float* __restrict__ W1_l0,
                                                        const float* __restrict__ W3_l1,
                                                        const float* __restrict__ W2_l1,
                                                        const float* __restrict__ W1_l1,
                                                        float* __restrict__ out) {
    extern __shared__ __align__(16) float4 s_coef[];   // [E_N * NT] = 154.9 KB
    __shared__ float sw30[E_N][5], sw31[E_N][7];
    __shared__ float sw20[E_N][2], sw21[E_N][3];
    __shared__ float sw10[E_N], sw11[E_N];
    int c   = blockIdx.x;
    int tid = threadIdx.x;

    // ---- stage per-channel species weights ----------------------------------
    if (tid < E_N * 5) sw30[tid / 5][tid % 5] = W3_l0[tid * C_N + c];
    if (tid < E_N * 7) sw31[tid / 7][tid % 7] = W3_l1[tid * C_N + c];
    if (tid < E_N * 2) sw20[tid / 2][tid % 2] = W2_l0[tid * C_N + c];
    if (tid < E_N * 3) sw21[tid / 3][tid % 3] = W2_l1[tid * C_N + c];
    if (tid < E_N) { sw10[tid] = W1_l0[tid * C_N + c]; sw11[tid] = W1_l1[tid * C_N + c]; }
    __syncthreads();

    // ---- fold: coefficients for all species, straight into SMEM -------------
    for (int t = tid; t < NT3; t += NPMAX) {
        float4 A0 = reinterpret_cast<const float4*>(&g_U3S[0][t][0])[0];
        float4 A1 = reinterpret_cast<const float4*>(&g_U3S[0][t][0])[1];
        float4 B0 = reinterpret_cast<const float4*>(&g_U3S[1][t][0])[0];
        float4 B1 = reinterpret_cast<const float4*>(&g_U3S[1][t][0])[1];
        float4 C0 = reinterpret_cast<const float4*>(&g_U3S[2][t][0])[0];
        float4 C1 = reinterpret_cast<const float4*>(&g_U3S[2][t][0])[1];
        float4 D0 = reinterpret_cast<const float4*>(&g_U3S[3][t][0])[0];
        float4 D1 = reinterpret_cast<const float4*>(&g_U3S[3][t][0])[1];
#pragma unroll
        for (int e = 0; e < E_N; e++) {
            float c0 = A0.x*sw30[e][0] + A0.y*sw30[e][1] + A0.z*sw30[e][2]
                     + A0.w*sw30[e][3] + A1.x*sw30[e][4];
            float c1 = B0.x*sw31[e][0] + B0.y*sw31[e][1] + B0.z*sw31[e][2]
                     + B0.w*sw31[e][3] + B1.x*sw31[e][4] + B1.y*sw31[e][5] + B1.z*sw31[e][6];
            float c2 = C0.x*sw31[e][0] + C0.y*sw31[e][1] + C0.z*sw31[e][2]
                     + C0.w*sw31[e][3] + C1.x*sw31[e][4] + C1.y*sw31[e][5] + C1.z*sw31[e][6];
            float c3 = D0.x*sw31[e][0] + D0.y*sw31[e][1] + D0.z*sw31[e][2]
                     + D0.w*sw31[e][3] + D1.x*sw31[e][4] + D1.y*sw31[e][5] + D1.z*sw31[e][6];
            s_coef[e * NT + t] = make_float4(c0, c1, c2, c3);
        }
    }
    for (int t = tid; t < NT2; t += NPMAX) {
        float4 Q0 = reinterpret_cast<const float4*>(&g_U2S[0][t][0])[0];
        float4 Q1 = reinterpret_cast<const float4*>(&g_U2S[1][t][0])[0];
        float4 Q2 = reinterpret_cast<const float4*>(&g_U2S[2][t][0])[0];
        float4 Q3 = reinterpret_cast<const float4*>(&g_U2S[3][t][0])[0];
#pragma unroll
        for (int e = 0; e < E_N; e++) {
            float c0 = Q0.x*sw20[e][0] + Q0.y*sw20[e][1];
            float c1 = Q1.x*sw21[e][0] + Q1.y*sw21[e][1] + Q1.z*sw21[e][2];
            float c2 = Q2.x*sw21[e][0] + Q2.y*sw21[e][1] + Q2.z*sw21[e][2];
            float c3 = Q3.x*sw21[e][0] + Q3.y*sw21[e][1] + Q3.z*sw21[e][2];
            s_coef[e * NT + NT3 + t] = make_float4(c0, c1, c2, c3);
        }
    }
    if (tid < I_N) {
        int i = tid;
#pragma unroll
        for (int e = 0; e < E_N; e++) {
            s_coef[e * NT + NT3 + NT2 + i] =
                make_float4(g_U1S[0][i] * sw10[e], g_U1S[1][i] * sw11[e],
                            g_U1S[2][i] * sw11[e], g_U1S[3][i] * sw11[e]);
        }
    }
    __syncthreads();

    // ---- eval: one same-species pair per thread ------------------------------
    if (tid >= g_npairs) return;
    int bA = g_pA[tid];
    int bB = g_pB[tid];
    int e  = g_pE[tid];
    const float4* base = s_coef + e * NT;

    float x0[16], x1[16];
    {
        const float4* xp = reinterpret_cast<const float4*>(a_i + (bA * C_N + c) * I_N);
        float4 v0 = xp[0], v1 = xp[1], v2 = xp[2], v3 = xp[3];
        x0[0]=v0.x;  x0[1]=v0.y;  x0[2]=v0.z;  x0[3]=v0.w;
        x0[4]=v1.x;  x0[5]=v1.y;  x0[6]=v1.z;  x0[7]=v1.w;
        x0[8]=v2.x;  x0[9]=v2.y;  x0[10]=v2.z; x0[11]=v2.w;
        x0[12]=v3.x; x0[13]=v3.y; x0[14]=v3.z; x0[15]=v3.w;
    }
    {
        const float4* xp = reinterpret_cast<const float4*>(a_i + (bB * C_N + c) * I_N);
        float4 v0 = xp[0], v1 = xp[1], v2 = xp[2], v3 = xp[3];
        x1[0]=v0.x;  x1[1]=v0.y;  x1[2]=v0.z;  x1[3]=v0.w;
        x1[4]=v1.x;  x1[5]=v1.y;  x1[6]=v1.z;  x1[7]=v1.w;
        x1[8]=v2.x;  x1[9]=v2.y;  x1[10]=v2.z; x1[11]=v2.w;
        x1[12]=v3.x; x1[13]=v3.y; x1[14]=v3.z; x1[15]=v3.w;
    }

    float o00 = 0.f, o01 = 0.f, o02 = 0.f, o03 = 0.f;
    float o10 = 0.f, o11 = 0.f, o12 = 0.f, o13 = 0.f;
    int t = 0, tp = 0;
#pragma unroll
    for (int a = 0; a < I_N; a++) {
        float t200, t201, t202, t203, t210, t211, t212, t213;
        float4 cl = base[NT3 + NT2 + a];   // linear coef A1_a
#pragma unroll
        for (int b2 = a; b2 < I_N; b2++) {
            float4 cq = base[NT3 + tp]; tp++;
            float t300, t301, t302, t303, t310, t311, t312, t313;
            {
                float4 cf = base[t]; t++;   // c3 == b2 term absorbs A2_ab
                t300 = fmaf(cf.x, x0[b2], cq.x);  t310 = fmaf(cf.x, x1[b2], cq.x);
                t301 = fmaf(cf.y, x0[b2], cq.y);  t311 = fmaf(cf.y, x1[b2], cq.y);
                t302 = fmaf(cf.z, x0[b2], cq.z);  t312 = fmaf(cf.z, x1[b2], cq.z);
                t303 = fmaf(cf.w, x0[b2], cq.w);  t313 = fmaf(cf.w, x1[b2], cq.w);
            }
#pragma unroll
            for (int c3 = b2 + 1; c3 < I_N; c3++) {
                float4 cf = base[t]; t++;
                t300 = fmaf(cf.x, x0[c3], t300);  t310 = fmaf(cf.x, x1[c3], t310);
                t301 = fmaf(cf.y, x0[c3], t301);  t311 = fmaf(cf.y, x1[c3], t311);
                t302 = fmaf(cf.z, x0[c3], t302);  t312 = fmaf(cf.z, x1[c3], t312);
                t303 = fmaf(cf.w, x0[c3], t303);  t313 = fmaf(cf.w, x1[c3], t313);
            }
            if (b2 == a) {   // first b-fold absorbs A1_a
                t200 = fmaf(t300, x0[b2], cl.x);  t210 = fmaf(t310, x1[b2], cl.x);
                t201 = fmaf(t301, x0[b2], cl.y);  t211 = fmaf(t311, x1[b2], cl.y);
                t202 = fmaf(t302, x0[b2], cl.z);  t212 = fmaf(t312, x1[b2], cl.z);
                t203 = fmaf(t303, x0[b2], cl.w);  t213 = fmaf(t313, x1[b2], cl.w);
            } else {
                t200 = fmaf(t300, x0[b2], t200);  t210 = fmaf(t310, x1[b2], t210);
                t201 = fmaf(t301, x0[b2], t201);  t211 = fmaf(t311, x1[b2], t211);
                t202 = fmaf(t302, x0[b2], t202);  t212 = fmaf(t312, x1[b2], t212);
                t203 = fmaf(t303, x0[b2], t203);  t213 = fmaf(t313, x1[b2], t213);
            }
        }
        o00 = fmaf(t200, x0[a], o00);  o10 = fmaf(t210, x1[a], o10);
        o01 = fmaf(t201, x0[a], o01);  o11 = fmaf(t211, x1[a], o11);
        o02 = fmaf(t202, x0[a], o02);  o12 = fmaf(t212, x1[a], o12);
        o03 = fmaf(t203, x0[a], o03);  o13 = fmaf(t213, x1[a], o13);
    }

    // output layout: [b, 512] = concat(out0[b, c], out1[b, c*3+m])
    {
        float* ob = out + bA * 512;
        ob[c]               = o00;
        ob[128 + c * 3 + 0] = o01;
        ob[128 + c * 3 + 1] = o02;
        ob[128 + c * 3 + 2] = o03;
    }
    {   // self-pair (odd tail): same addr, same values — benign rewrite
        float* ob = out + bB * 512;
        ob[c]               = o10;
        ob[128 + c * 3 + 0] = o11;
        ob[128 + c * 3 + 1] = o12;
        ob[128 + c * 3 + 2] = o13;
    }
}

// ---------------- launch --------------------------------------------------------
extern "C" void kernel_launch(void* const* d_in, const int* in_sizes, int n_in,
                              void* d_out, int out_size) {
    const float* a_i   = (const float*)d_in[0];
    const float* na    = (const float*)d_in[1];
    const float* U3_l0 = (const float*)d_in[2];
    const float* U2_l0 = (const float*)d_in[3];
    const float* U1_l0 = (const float*)d_in[4];
    const float* W3_l0 = (const float*)d_in[5];
    const float* W2_l0 = (const float*)d_in[6];
    const float* W1_l0 = (const float*)d_in[7];
    const float* U3_l1 = (const float*)d_in[8];
    const float* U2_l1 = (const float*)d_in[9];
    const float* U1_l1 = (const float*)d_in[10];
    const float* W3_l1 = (const float*)d_in[11];
    const float* W2_l1 = (const float*)d_in[12];
    const float* W1_l1 = (const float*)d_in[13];
    float* out = (float*)d_out;

    const int smem_bytes = E_N * NT * (int)sizeof(float4);  // 154880
    cudaFuncSetAttribute(main_kernel, cudaFuncAttributeMaxDynamicSharedMemorySize,
                         smem_bytes);

    prep_kernel<<<33, 1024>>>(na, U3_l0, U3_l1, U2_l0, U2_l1, U1_l0, U1_l1);
    main_kernel<<<C_N, NPMAX, smem_bytes>>>(a_i, W3_l0, W2_l0, W1_l0,
                                            W3_l1, W2_l1, W1_l1, out);
}

// round 14
// speedup vs baseline: 1.1351x; 1.1351x over previous
#include <cuda_runtime.h>

#define B_N   1024
#define C_N   128
#define I_N   16
#define E_N   10
#define NT3   816           // cubic monomials i0<=i1<=i2
#define NT2   136           // quadratic monomials
#define NT    968           // 816 + 136 + 16
#define NCOMP 4
#define NPMAX 640           // >= max possible pairs (517)

// ---------------- device scratch (static globals; no allocation) ----------------
__device__ int   g_pA[NPMAX];
__device__ int   g_pB[NPMAX];
__device__ int   g_pE[NPMAX];
__device__ int   g_npairs;
__device__ __align__(32) float g_U3S[NCOMP][NT3][8];
__device__ __align__(16) float g_U2S[NCOMP][NT2][4];
__device__ float g_U1S[NCOMP][I_N];

// ---------------- kernel A: sort+pair (block 0) + U sym (blocks 1..32) ----------
__global__ void prep_kernel(const float* __restrict__ node_attrs,
                            const float* __restrict__ U3_l0,
                            const float* __restrict__ U3_l1,
                            const float* __restrict__ U2_l0,
                            const float* __restrict__ U2_l1,
                            const float* __restrict__ U1_l0,
                            const float* __restrict__ U1_l1) {
    int tid = threadIdx.x;   // 1024
    if (blockIdx.x == 0) {
        __shared__ int s_hist[E_N], s_off[E_N], s_start[E_N], s_end[E_N], s_pbase[E_N];
        __shared__ int s_perm[B_N];
        if (tid < E_N) s_hist[tid] = 0;
        __syncthreads();
        const float* na = node_attrs + tid * E_N;
        int e = 0;
#pragma unroll
        for (int j = 0; j < E_N; j++) if (na[j] > 0.5f) e = j;
        atomicAdd(&s_hist[e], 1);
        __syncthreads();
        if (tid == 0) {
            int acc = 0, pacc = 0;
            for (int j = 0; j < E_N; j++) {
                s_start[j] = acc; s_off[j] = acc; s_pbase[j] = pacc;
                pacc += (s_hist[j] + 1) >> 1;
                acc  += s_hist[j];
                s_end[j] = acc;
            }
            g_npairs = pacc;
        }
        __syncthreads();
        int pos = atomicAdd(&s_off[e], 1);
        s_perm[pos] = tid;
        __syncthreads();
        int off = pos - s_start[e];
        if ((off & 1) == 0) {
            int p    = s_pbase[e] + (off >> 1);
            int posB = (pos + 1 < s_end[e]) ? pos + 1 : pos;  // odd tail: self-pair
            g_pA[p] = tid;
            g_pB[p] = s_perm[posB];
            g_pE[p] = e;
        }
        return;
    }

    int gtid = (blockIdx.x - 1) * blockDim.x + tid;   // 0..32767

    if (gtid < NCOMP * NT3 * 8) {
        int k    = gtid & 7;
        int t    = (gtid >> 3) % NT3;
        int comp = gtid / (NT3 * 8);
        int rem = t, a = 0;
        for (int ap = 0; ap < I_N; ap++) {
            int sz = (I_N - ap) * (I_N - ap + 1) / 2;
            if (rem < sz) { a = ap; break; }
            rem -= sz;
        }
        int b = a;
        for (int bp = a; bp < I_N; bp++) {
            int sz = I_N - bp;
            if (rem < sz) { b = bp; break; }
            rem -= sz;
        }
        int c = b + rem;
        float inv = (a == c) ? (1.f / 6.f) : ((a == b || b == c) ? 0.5f : 1.f);
        int kN; const float* U;
        if (comp == 0) { kN = 5; U = U3_l0; }
        else           { kN = 7; U = U3_l1 + (comp - 1) * (I_N * I_N * I_N * 7); }
        float s = 0.f;
        if (k < kN) {
            auto at = [&](int i0, int i1, int i2) {
                return U[((i0 * I_N + i1) * I_N + i2) * kN + k];
            };
            s = at(a,b,c) + at(a,c,b) + at(b,a,c) + at(b,c,a) + at(c,a,b) + at(c,b,a);
            s *= inv;
        }
        g_U3S[comp][t][k] = s;
    }
    if (gtid < NCOMP * NT2 * 4) {
        int k    = gtid & 3;
        int t    = (gtid >> 2) % NT2;
        int comp = gtid / (NT2 * 4);
        int rem = t, a = 0;
        for (int ap = 0; ap < I_N; ap++) {
            int sz = I_N - ap;
            if (rem < sz) { a = ap; break; }
            rem -= sz;
        }
        int b = a + rem;
        int kN; const float* U;
        if (comp == 0) { kN = 2; U = U2_l0; }
        else           { kN = 3; U = U2_l1 + (comp - 1) * (I_N * I_N * 3); }
        float s = 0.f;
        if (k < kN) {
            s = U[(a * I_N + b) * kN + k];
            if (a != b) s += U[(b * I_N + a) * kN + k];
        }
        g_U2S[comp][t][k] = s;
    }
    if (gtid < NCOMP * I_N) {
        int comp = gtid / I_N, i = gtid % I_N;
        g_U1S[comp][i] = (comp == 0) ? U1_l0[i] : U1_l1[(comp - 1) * I_N + i];
    }
}

// ---------------- kernel B: fused fold + evaluation, block = channel ------------
// 1024 threads, 32 warps. Coefficients in SMEM as TWO float2 arrays:
//   s01[e*NT+t] = {c0,c1},  s23[e*NT+t] = {c2,c3}   (155 KB total).
// Eval: half-task h of pair q computes comps {2h, 2h+1} for BOTH items of the
// pair -> per thread 968 broadcast LDS.64 + 3872 FMA. Same issue count as the
// R12 1-item body, but half the L1 wavefronts per pair; full 32-warp block.
__global__ void __launch_bounds__(1024, 1) main_kernel(const float* __restrict__ a_i,
                                                       const float* __restrict__ W3_l0,
                                                       const float* __restrict__ W2_l0,
                                                       const float* __restrict__ W1_l0,
                                                       const float* __restrict__ W3_l1,
                                                       const float* __restrict__ W2_l1,
                                                       const float* __restrict__ W1_l1,
                                                       float* __restrict__ out) {
    extern __shared__ __align__(16) float2 s_raw[];
    float2* s01 = s_raw;                 // [E_N * NT]
    float2* s23 = s_raw + E_N * NT;      // [E_N * NT]
    __shared__ float sw30[E_N][5], sw31[E_N][7];
    __shared__ float sw20[E_N][2], sw21[E_N][3];
    __shared__ float sw10[E_N], sw11[E_N];
    int c   = blockIdx.x;
    int tid = threadIdx.x;

    // ---- stage per-channel species weights ----------------------------------
    if (tid < E_N * 5) sw30[tid / 5][tid % 5] = W3_l0[tid * C_N + c];
    if (tid < E_N * 7) sw31[tid / 7][tid % 7] = W3_l1[tid * C_N + c];
    if (tid < E_N * 2) sw20[tid / 2][tid % 2] = W2_l0[tid * C_N + c];
    if (tid < E_N * 3) sw21[tid / 3][tid % 3] = W2_l1[tid * C_N + c];
    if (tid < E_N) { sw10[tid] = W1_l0[tid * C_N + c]; sw11[tid] = W1_l1[tid * C_N + c]; }
    __syncthreads();

    // ---- fold: coefficients for all species, straight into SMEM -------------
    for (int t = tid; t < NT3; t += 1024) {
        float4 A0 = reinterpret_cast<const float4*>(&g_U3S[0][t][0])[0];
        float4 A1 = reinterpret_cast<const float4*>(&g_U3S[0][t][0])[1];
        float4 B0 = reinterpret_cast<const float4*>(&g_U3S[1][t][0])[0];
        float4 B1 = reinterpret_cast<const float4*>(&g_U3S[1][t][0])[1];
        float4 C0 = reinterpret_cast<const float4*>(&g_U3S[2][t][0])[0];
        float4 C1 = reinterpret_cast<const float4*>(&g_U3S[2][t][0])[1];
        float4 D0 = reinterpret_cast<const float4*>(&g_U3S[3][t][0])[0];
        float4 D1 = reinterpret_cast<const float4*>(&g_U3S[3][t][0])[1];
#pragma unroll
        for (int e = 0; e < E_N; e++) {
            float c0 = A0.x*sw30[e][0] + A0.y*sw30[e][1] + A0.z*sw30[e][2]
                     + A0.w*sw30[e][3] + A1.x*sw30[e][4];
            float c1 = B0.x*sw31[e][0] + B0.y*sw31[e][1] + B0.z*sw31[e][2]
                     + B0.w*sw31[e][3] + B1.x*sw31[e][4] + B1.y*sw31[e][5] + B1.z*sw31[e][6];
            float c2 = C0.x*sw31[e][0] + C0.y*sw31[e][1] + C0.z*sw31[e][2]
                     + C0.w*sw31[e][3] + C1.x*sw31[e][4] + C1.y*sw31[e][5] + C1.z*sw31[e][6];
            float c3 = D0.x*sw31[e][0] + D0.y*sw31[e][1] + D0.z*sw31[e][2]
                     + D0.w*sw31[e][3] + D1.x*sw31[e][4] + D1.y*sw31[e][5] + D1.z*sw31[e][6];
            s01[e * NT + t] = make_float2(c0, c1);
            s23[e * NT + t] = make_float2(c2, c3);
        }
    }
    for (int t = tid; t < NT2; t += 1024) {
        float4 Q0 = reinterpret_cast<const float4*>(&g_U2S[0][t][0])[0];
        float4 Q1 = reinterpret_cast<const float4*>(&g_U2S[1][t][0])[0];
        float4 Q2 = reinterpret_cast<const float4*>(&g_U2S[2][t][0])[0];
        float4 Q3 = reinterpret_cast<const float4*>(&g_U2S[3][t][0])[0];
#pragma unroll
        for (int e = 0; e < E_N; e++) {
            float c0 = Q0.x*sw20[e][0] + Q0.y*sw20[e][1];
            float c1 = Q1.x*sw21[e][0] + Q1.y*sw21[e][1] + Q1.z*sw21[e][2];
            float c2 = Q2.x*sw21[e][0] + Q2.y*sw21[e][1] + Q2.z*sw21[e][2];
            float c3 = Q3.x*sw21[e][0] + Q3.y*sw21[e][1] + Q3.z*sw21[e][2];
            s01[e * NT + NT3 + t] = make_float2(c0, c1);
            s23[e * NT + NT3 + t] = make_float2(c2, c3);
        }
    }
    if (tid < I_N) {
        int i = tid;
#pragma unroll
        for (int e = 0; e < E_N; e++) {
            s01[e * NT + NT3 + NT2 + i] =
                make_float2(g_U1S[0][i] * sw10[e], g_U1S[1][i] * sw11[e]);
            s23[e * NT + NT3 + NT2 + i] =
                make_float2(g_U1S[2][i] * sw11[e], g_U1S[3][i] * sw11[e]);
        }
    }
    __syncthreads();

    // ---- eval: half-tasks (pair q, comp-half h) ------------------------------
    int np = g_npairs;
    for (int task = tid; task < 2 * np; task += 1024) {
        int h = (task >= np) ? 1 : 0;
        int q = task - h * np;
        int bA = g_pA[q];
        int bB = g_pB[q];
        const float2* base = (h ? s23 : s01) + g_pE[q] * NT;

        float x0[16], x1[16];
        {
            const float4* xp = reinterpret_cast<const float4*>(a_i + (bA * C_N + c) * I_N);
            float4 v0 = xp[0], v1 = xp[1], v2 = xp[2], v3 = xp[3];
            x0[0]=v0.x;  x0[1]=v0.y;  x0[2]=v0.z;  x0[3]=v0.w;
            x0[4]=v1.x;  x0[5]=v1.y;  x0[6]=v1.z;  x0[7]=v1.w;
            x0[8]=v2.x;  x0[9]=v2.y;  x0[10]=v2.z; x0[11]=v2.w;
            x0[12]=v3.x; x0[13]=v3.y; x0[14]=v3.z; x0[15]=v3.w;
        }
        {
            const float4* xp = reinterpret_cast<const float4*>(a_i + (bB * C_N + c) * I_N);
            float4 v0 = xp[0], v1 = xp[1], v2 = xp[2], v3 = xp[3];
            x1[0]=v0.x;  x1[1]=v0.y;  x1[2]=v0.z;  x1[3]=v0.w;
            x1[4]=v1.x;  x1[5]=v1.y;  x1[6]=v1.z;  x1[7]=v1.w;
            x1[8]=v2.x;  x1[9]=v2.y;  x1[10]=v2.z; x1[11]=v2.w;
            x1[12]=v3.x; x1[13]=v3.y; x1[14]=v3.z; x1[15]=v3.w;
        }

        // comps u = 2h (x lane of float2), v = 2h+1 (y lane); items A, B
        float ouA = 0.f, ouB = 0.f, ovA = 0.f, ovB = 0.f;
        int t = 0, tp = 0;
#pragma unroll
        for (int a = 0; a < I_N; a++) {
            float t2uA, t2uB, t2vA, t2vB;
            float2 cl = base[NT3 + NT2 + a];
#pragma unroll
            for (int b2 = a; b2 < I_N; b2++) {
                float2 cq = base[NT3 + tp]; tp++;
                float t3uA, t3uB, t3vA, t3vB;
                {
                    float2 cf = base[t]; t++;   // c3 == b2 absorbs quad coef
                    t3uA = fmaf(cf.x, x0[b2], cq.x);  t3uB = fmaf(cf.x, x1[b2], cq.x);
                    t3vA = fmaf(cf.y, x0[b2], cq.y);  t3vB = fmaf(cf.y, x1[b2], cq.y);
                }
#pragma unroll
                for (int c3 = b2 + 1; c3 < I_N; c3++) {
                    float2 cf = base[t]; t++;
                    t3uA = fmaf(cf.x, x0[c3], t3uA);  t3uB = fmaf(cf.x, x1[c3], t3uB);
                    t3vA = fmaf(cf.y, x0[c3], t3vA);  t3vB = fmaf(cf.y, x1[c3], t3vB);
                }
                if (b2 == a) {   // first b-fold absorbs linear coef
                    t2uA = fmaf(t3uA, x0[b2], cl.x);  t2uB = fmaf(t3uB, x1[b2], cl.x);
                    t2vA = fmaf(t3vA, x0[b2], cl.y);  t2vB = fmaf(t3vB, x1[b2], cl.y);
                } else {
                    t2uA = fmaf(t3uA, x0[b2], t2uA);  t2uB = fmaf(t3uB, x1[b2], t2uB);
                    t2vA = fmaf(t3vA, x0[b2], t2vA);  t2vB = fmaf(t3vB, x1[b2], t2vB);
                }
            }
            ouA = fmaf(t2uA, x0[a], ouA);  ouB = fmaf(t2uB, x1[a], ouB);
            ovA = fmaf(t2vA, x0[a], ovA);  ovB = fmaf(t2vB, x1[a], ovB);
        }

        // output: [b, 512] = concat(out0[b,c], out1[b, c*3+m])
        // h=0 -> comps 0 (ob[c]) and 1 (ob[128+3c]); h=1 -> comps 2, 3
        int addrU = h ? (128 + c * 3 + 1) : c;
        int addrV = h ? (128 + c * 3 + 2) : (128 + c * 3);
        out[bA * 512 + addrU] = ouA;
        out[bA * 512 + addrV] = ovA;
        out[bB * 512 + addrU] = ouB;   // self-pair: benign duplicate write
        out[bB * 512 + addrV] = ovB;
    }
}

// ---------------- launch --------------------------------------------------------
extern "C" void kernel_launch(void* const* d_in, const int* in_sizes, int n_in,
                              void* d_out, int out_size) {
    const float* a_i   = (const float*)d_in[0];
    const float* na    = (const float*)d_in[1];
    const float* U3_l0 = (const float*)d_in[2];
    const float* U2_l0 = (const float*)d_in[3];
    const float* U1_l0 = (const float*)d_in[4];
    const float* W3_l0 = (const float*)d_in[5];
    const float* W2_l0 = (const float*)d_in[6];
    const float* W1_l0 = (const float*)d_in[7];
    const float* U3_l1 = (const float*)d_in[8];
    const float* U2_l1 = (const float*)d_in[9];
    const float* U1_l1 = (const float*)d_in[10];
    const float* W3_l1 = (const float*)d_in[11];
    const float* W2_l1 = (const float*)d_in[12];
    const float* W1_l1 = (const float*)d_in[13];
    float* out = (float*)d_out;

    const int smem_bytes = 2 * E_N * NT * (int)sizeof(float2);  // 154880
    cudaFuncSetAttribute(main_kernel, cudaFuncAttributeMaxDynamicSharedMemorySize,
                         smem_bytes);

    prep_kernel<<<33, 1024>>>(na, U3_l0, U3_l1, U2_l0, U2_l1, U1_l0, U1_l1);
    main_kernel<<<C_N, 1024, smem_bytes>>>(a_i, W3_l0, W2_l0, W1_l0,
                                           W3_l1, W2_l1, W1_l1, out);
}